// round 13
// baseline (speedup 1.0000x reference)
#include <cuda_runtime.h>
#include <cuda_fp16.h>
#include <cstdint>
#define DI __device__ __forceinline__
namespace {
constexpr int INF=1024, OUTF=1024, KD=20480;
constexpr int KC=128, NCH=KD/KC;     // 160 chunks
constexpr int HTST=128*64*2;         // 16 KB half-tile (64 halves of k)
constexpr int TST=2*HTST;            // 32 KB per operand-stage
constexpr int NSTG=3;
constexpr int SMEMSZ=NSTG*2*TST;     // 192 KB
constexpr int NTHR=512;              // 16 warps: 4M x 4N, 32x32 warp tiles

__device__ __align__(16) __half AH[(size_t)2048*KD];
__device__ __align__(16) __half WH[(size_t)OUTF*KD];

DI uint32_t swz(uint32_t o){return o^((o>>3)&0x70);}
DI uint32_t s2u(const void*p){uint32_t a;asm("{ .reg .u64 t; cvta.to.shared.u64 t, %1; cvt.u32.u64 %0, t; }":"=r"(a):"l"(p));return a;}
DI void cp16(uint32_t d,const void*s){asm volatile("cp.async.cg.shared.global [%0], [%1], 16;"::"r"(d),"l"(s):"memory");}
DI void cpc(){asm volatile("cp.async.commit_group;":::"memory");}
#define CPW(n) asm volatile("cp.async.wait_group %0;"::"n"(n):"memory")
DI void ldsm4(uint32_t*r,uint32_t a){asm volatile("ldmatrix.sync.aligned.m8n8.x4.shared.b16 {%0,%1,%2,%3}, [%4];":"=r"(r[0]),"=r"(r[1]),"=r"(r[2]),"=r"(r[3]):"r"(a));}
DI void mma(float*d,const uint32_t*a,const uint32_t*b){
  asm volatile("mma.sync.aligned.m16n8k16.row.col.f32.f16.f16.f32 {%0,%1,%2,%3},{%4,%5,%6,%7},{%8,%9},{%0,%1,%2,%3};"
  :"+f"(d[0]),"+f"(d[1]),"+f"(d[2]),"+f"(d[3])
  :"r"(a[0]),"r"(a[1]),"r"(a[2]),"r"(a[3]),"r"(b[0]),"r"(b[1]));}
DI float ex2f(float x){float r;asm("ex2.approx.ftz.f32 %0, %1;":"=f"(r):"f"(x));return r;}

__global__ void __launch_bounds__(256) kprep(const float* __restrict__ X,
                                            const float* __restrict__ W){
  if(blockIdx.x<2048){
    int b=blockIdx.x; const float* xr=X+(size_t)b*INF;
    __half* dst=AH+(size_t)b*KD;
    for(int g=threadIdx.x; g<KD/8; g+=256){
      int j0=g*8;
      int i0=j0/20, k0=j0-20*i0;
      float xa=__ldg(xr+i0);
      float xb=(k0>12)?__ldg(xr+i0+1):xa;
      uint32_t w[4];
#pragma unroll
      for(int u=0;u<4;++u){
        float e[2];
#pragma unroll
        for(int v=0;v<2;++v){
          int k=k0+2*u+v;
          bool hi=k>=20;
          float xv=hi?xb:xa;
          float kf=(float)(hi?k-20:k);
          float t=fmaf(4.75f,xv,9.5f-kf);
          e[v]=ex2f(-0.72134752044448170f*t*t);
        }
        __half2 h=__floats2half2_rn(e[0],e[1]);
        w[u]=*reinterpret_cast<uint32_t*>(&h);
      }
      uint4 o={w[0],w[1],w[2],w[3]};
      *reinterpret_cast<uint4*>(dst+j0)=o;
    }
  } else {
    size_t g=(size_t)(blockIdx.x-2048)*256+threadIdx.x;
    const float4* s=reinterpret_cast<const float4*>(W)+2*g;
    float4 p=__ldg(s), q=__ldg(s+1);
    __half2 h0=__floats2half2_rn(p.x,p.y),h1=__floats2half2_rn(p.z,p.w);
    __half2 h2=__floats2half2_rn(q.x,q.y),h3=__floats2half2_rn(q.z,q.w);
    uint4 o={*(uint32_t*)&h0,*(uint32_t*)&h1,*(uint32_t*)&h2,*(uint32_t*)&h3};
    reinterpret_cast<uint4*>(WH)[g]=o;
  }
}

__global__ void __launch_bounds__(NTHR,1) kgemm(float* __restrict__ out){
  extern __shared__ char sm[];
  const uint32_t sb=s2u(sm);
  const int tid=threadIdx.x, wid=tid>>5, ln=tid&31;
  const int m0=(blockIdx.x&15)*128, n0=(blockIdx.x>>4)*128;
  const __half* Ab=AH+(size_t)m0*KD;
  const __half* Bb=WH+(size_t)n0*KD;
  const int wm=wid>>2, wn=wid&3;       // 4x4 warp grid, 32x32 tiles
  float c[2][4][4];
#pragma unroll
  for(int i=0;i<2;++i)
#pragma unroll
    for(int j=0;j<4;++j)
#pragma unroll
      for(int k=0;k<4;++k) c[i][j][k]=0.f;

  int lst=0;
  auto load=[&](int ch){
    uint32_t s=sb+(uint32_t)lst*2u*TST;
    if(++lst==NSTG) lst=0;
#pragma unroll
    for(int q=0;q<4;++q){
      int seg=tid+q*NTHR;                 // 2048 segs per operand
      int half=seg>>10, rem=seg&1023;
      int r=rem>>3, c16=rem&7;
      uint32_t off=(uint32_t)half*HTST+swz((uint32_t)(r*128+c16*16));
      const size_t go=(size_t)r*KD+(size_t)ch*KC+half*64+c16*8;
      cp16(s+off, Ab+go);
      cp16(s+TST+off, Bb+go);
    }
    cpc();
  };
  load(0); load(1);

  // per-warp ldsm row addresses (row-dependent swizzle xor precomputed)
  int arow[2], brow[2];
  uint32_t arx[2], brx[2];
#pragma unroll
  for(int mi=0;mi<2;++mi){
    arow[mi]=wm*32+mi*16+(ln&15); arx[mi]=(uint32_t)((arow[mi]&7)<<4);
  }
#pragma unroll
  for(int ni=0;ni<2;++ni){
    brow[ni]=wn*32+ni*16+(ln&7)+(ln&8); brx[ni]=(uint32_t)((brow[ni]&7)<<4);
  }
  const uint32_t lcol=(uint32_t)((ln>>4)*16);

  int cst=0;
  for(int ch=0;ch<NCH;++ch){
    CPW(1);
    __syncthreads();
    if(ch+2<NCH) load(ch+2); else cpc();
    const uint32_t sa=sb+(uint32_t)cst*2u*TST, sB=sa+TST;
    if(++cst==NSTG) cst=0;

    uint32_t a[2][2][4], b[2][2][4];
    auto frag=[&](int ks, uint32_t (*af)[4], uint32_t (*bf)[4]){
      const uint32_t kb=(uint32_t)((ks&3)*32)+lcol;
      const uint32_t hb=(uint32_t)(ks>>2)*HTST;
#pragma unroll
      for(int mi=0;mi<2;++mi)
        ldsm4(af[mi], sa+hb+(uint32_t)(arow[mi]*128)+(kb^arx[mi]));
#pragma unroll
      for(int ni=0;ni<2;++ni)
        ldsm4(bf[ni], sB+hb+(uint32_t)(brow[ni]*128)+(kb^brx[ni]));
    };
    frag(0, a[0], b[0]);
#pragma unroll
    for(int ks=0;ks<8;++ks){
      const int cur=ks&1, nxt=cur^1;
      if(ks<7) frag(ks+1, a[nxt], b[nxt]);
#pragma unroll
      for(int mi=0;mi<2;++mi)
#pragma unroll
        for(int ni=0;ni<2;++ni){
          uint32_t b0[2]={b[cur][ni][0],b[cur][ni][2]};
          uint32_t b1[2]={b[cur][ni][1],b[cur][ni][3]};
          mma(c[mi][2*ni],   a[cur][mi], b0);
          mma(c[mi][2*ni+1], a[cur][mi], b1);
        }
    }
  }

  float* dst=out+(size_t)m0*OUTF+n0;
#pragma unroll
  for(int mi=0;mi<2;++mi)
#pragma unroll
    for(int j=0;j<4;++j){
      int r0=wm*32+mi*16+(ln>>2);
      int col=wn*32+(j>>1)*16+(j&1)*8+(ln&3)*2;
      float2 v0; v0.x=c[mi][j][0]; v0.y=c[mi][j][1];
      float2 v1; v1.x=c[mi][j][2]; v1.y=c[mi][j][3];
      *reinterpret_cast<float2*>(dst+(size_t)r0*OUTF+col)=v0;
      *reinterpret_cast<float2*>(dst+(size_t)(r0+8)*OUTF+col)=v1;
    }
}
} // namespace

extern "C" void kernel_launch(void* const* d_in, const int* in_sizes, int n_in,
                              void* d_out, int out_size){
  (void)in_sizes;(void)n_in;(void)out_size;
  const float* X=(const float*)d_in[0];
  const float* W=(const float*)d_in[1];
  float* out=(float*)d_out;
  kprep<<<12288,256>>>(X,W);
  cudaFuncSetAttribute(kgemm, cudaFuncAttributeMaxDynamicSharedMemorySize, SMEMSZ);
  kgemm<<<128,NTHR,SMEMSZ>>>(out);
}

// round 14
// speedup vs baseline: 1.6432x; 1.6432x over previous
#include <cuda_runtime.h>
#include <cuda_fp16.h>
#include <cstdint>
#define DI __device__ __forceinline__
namespace {
constexpr int INF=1024, OUTF=1024, KD=20480;
constexpr int TM=128, TN=64, KC=64, NCH=KD/KC;   // 320 chunks
constexpr int ASTG=TM*KC*2;          // 16 KB
constexpr int BSTG=TN*KC*2;          // 8 KB
constexpr int STG=ASTG+BSTG;         // 24 KB / stage
constexpr int NSTG=4;
constexpr int SMEMSZ=NSTG*STG;       // 96 KB -> 2 CTAs/SM
constexpr int NTHR=256;              // 8 warps: 4M x 2N, 32x32 warp tiles

__device__ __align__(16) __half AH[(size_t)2048*KD];
__device__ __align__(16) __half WH[(size_t)OUTF*KD];

DI uint32_t swz(uint32_t o){return o^((o>>3)&0x70);}
DI uint32_t s2u(const void*p){uint32_t a;asm("{ .reg .u64 t; cvta.to.shared.u64 t, %1; cvt.u32.u64 %0, t; }":"=r"(a):"l"(p));return a;}
DI void cp16(uint32_t d,const void*s){asm volatile("cp.async.cg.shared.global [%0], [%1], 16;"::"r"(d),"l"(s):"memory");}
DI void cpc(){asm volatile("cp.async.commit_group;":::"memory");}
#define CPW(n) asm volatile("cp.async.wait_group %0;"::"n"(n):"memory")
DI void ldsm4(uint32_t*r,uint32_t a){asm volatile("ldmatrix.sync.aligned.m8n8.x4.shared.b16 {%0,%1,%2,%3}, [%4];":"=r"(r[0]),"=r"(r[1]),"=r"(r[2]),"=r"(r[3]):"r"(a));}
DI void mma(float*d,const uint32_t*a,const uint32_t*b){
  asm volatile("mma.sync.aligned.m16n8k16.row.col.f32.f16.f16.f32 {%0,%1,%2,%3},{%4,%5,%6,%7},{%8,%9},{%0,%1,%2,%3};"
  :"+f"(d[0]),"+f"(d[1]),"+f"(d[2]),"+f"(d[3])
  :"r"(a[0]),"r"(a[1]),"r"(a[2]),"r"(a[3]),"r"(b[0]),"r"(b[1]));}
DI float ex2f(float x){float r;asm("ex2.approx.ftz.f32 %0, %1;":"=f"(r):"f"(x));return r;}

__global__ void __launch_bounds__(256) kprep(const float* __restrict__ X,
                                            const float* __restrict__ W){
  if(blockIdx.x<2048){
    int b=blockIdx.x; const float* xr=X+(size_t)b*INF;
    __half* dst=AH+(size_t)b*KD;
    for(int g=threadIdx.x; g<KD/8; g+=256){
      int j0=g*8;
      int i0=j0/20, k0=j0-20*i0;
      float xa=__ldg(xr+i0);
      float xb=(k0>12)?__ldg(xr+i0+1):xa;
      uint32_t w[4];
#pragma unroll
      for(int u=0;u<4;++u){
        float e[2];
#pragma unroll
        for(int v=0;v<2;++v){
          int k=k0+2*u+v;
          bool hi=k>=20;
          float xv=hi?xb:xa;
          float kf=(float)(hi?k-20:k);
          float t=fmaf(4.75f,xv,9.5f-kf);
          e[v]=ex2f(-0.72134752044448170f*t*t);
        }
        __half2 h=__floats2half2_rn(e[0],e[1]);
        w[u]=*reinterpret_cast<uint32_t*>(&h);
      }
      uint4 o={w[0],w[1],w[2],w[3]};
      *reinterpret_cast<uint4*>(dst+j0)=o;
    }
  } else {
    size_t g=(size_t)(blockIdx.x-2048)*256+threadIdx.x;
    const float4* s=reinterpret_cast<const float4*>(W)+2*g;
    float4 p=__ldg(s), q=__ldg(s+1);
    __half2 h0=__floats2half2_rn(p.x,p.y),h1=__floats2half2_rn(p.z,p.w);
    __half2 h2=__floats2half2_rn(q.x,q.y),h3=__floats2half2_rn(q.z,q.w);
    uint4 o={*(uint32_t*)&h0,*(uint32_t*)&h1,*(uint32_t*)&h2,*(uint32_t*)&h3};
    reinterpret_cast<uint4*>(WH)[g]=o;
  }
}

__global__ void __launch_bounds__(NTHR,2) kgemm(float* __restrict__ out){
  extern __shared__ char sm[];
  const uint32_t sb=s2u(sm);
  const int tid=threadIdx.x, wid=tid>>5, ln=tid&31;
  const int m0=(blockIdx.x&15)*TM, n0=(blockIdx.x>>4)*TN;
  const __half* Ab=AH+(size_t)m0*KD;
  const __half* Bb=WH+(size_t)n0*KD;
  const int wm=wid>>1, wn=wid&1;       // 4x2 warp grid, 32x32 tiles
  float c[2][4][4];
#pragma unroll
  for(int i=0;i<2;++i)
#pragma unroll
    for(int j=0;j<4;++j)
#pragma unroll
      for(int k=0;k<4;++k) c[i][j][k]=0.f;

  int lst=0;
  auto load=[&](int ch){
    uint32_t s=sb+(uint32_t)lst*STG;
    if(++lst==NSTG) lst=0;
#pragma unroll
    for(int q=0;q<4;++q){               // A: 1024 segs
      int seg=tid+q*NTHR; int r=seg>>3,c16=seg&7;
      cp16(s+swz((uint32_t)(r*128+c16*16)),
           Ab+(size_t)r*KD+(size_t)ch*KC+c16*8);
    }
#pragma unroll
    for(int q=0;q<2;++q){               // B: 512 segs
      int seg=tid+q*NTHR; int r=seg>>3,c16=seg&7;
      cp16(s+ASTG+swz((uint32_t)(r*128+c16*16)),
           Bb+(size_t)r*KD+(size_t)ch*KC+c16*8);
    }
    cpc();
  };
  load(0); load(1); load(2);

  // per-warp ldsm rows
  int arow[2], brow[2];
#pragma unroll
  for(int mi=0;mi<2;++mi) arow[mi]=wm*32+mi*16+(ln&15);
#pragma unroll
  for(int ni=0;ni<2;++ni) brow[ni]=wn*32+ni*16+(ln&7)+(ln&8);
  const uint32_t lcol=(uint32_t)((ln>>4)*16);

  int cst=0;
  uint32_t a[2][2][4], b[2][2][4];
  auto frag=[&](uint32_t stage, int ks, uint32_t (*af)[4], uint32_t (*bf)[4]){
    const uint32_t sa=sb+stage*STG, sB=sa+ASTG;
    const uint32_t kb=(uint32_t)(ks*32)+lcol;
#pragma unroll
    for(int mi=0;mi<2;++mi)
      ldsm4(af[mi], sa+swz((uint32_t)(arow[mi]*128)+kb));
#pragma unroll
    for(int ni=0;ni<2;++ni)
      ldsm4(bf[ni], sB+swz((uint32_t)(brow[ni]*128)+kb));
  };

  CPW(2); __syncthreads();
  frag(0,0,a[0],b[0]);

  for(int ch=0;ch<NCH;++ch){
    const uint32_t cur_st=(uint32_t)cst;
    const uint32_t nxt_st=(uint32_t)((cst+1==NSTG)?0:cst+1);
    if(++cst==NSTG) cst=0;
#pragma unroll
    for(int ks=0;ks<4;++ks){
      const int cur=ks&1, nxt=cur^1;
      if(ks<3){
        frag(cur_st, ks+1, a[nxt], b[nxt]);
      } else {
        CPW(1);
        __syncthreads();
        if(ch+3<NCH) load(ch+3); else cpc();
        if(ch+1<NCH) frag(nxt_st, 0, a[nxt], b[nxt]);
      }
#pragma unroll
      for(int mi=0;mi<2;++mi)
#pragma unroll
        for(int ni=0;ni<2;++ni){
          uint32_t b0[2]={b[cur][ni][0],b[cur][ni][2]};
          uint32_t b1[2]={b[cur][ni][1],b[cur][ni][3]};
          mma(c[mi][2*ni],   a[cur][mi], b0);
          mma(c[mi][2*ni+1], a[cur][mi], b1);
        }
    }
  }

  float* dst=out+(size_t)m0*OUTF+n0;
#pragma unroll
  for(int mi=0;mi<2;++mi)
#pragma unroll
    for(int j=0;j<4;++j){
      int r0=wm*32+mi*16+(ln>>2);
      int col=wn*32+(j>>1)*16+(j&1)*8+(ln&3)*2;
      float2 v0; v0.x=c[mi][j][0]; v0.y=c[mi][j][1];
      float2 v1; v1.x=c[mi][j][2]; v1.y=c[mi][j][3];
      *reinterpret_cast<float2*>(dst+(size_t)r0*OUTF+col)=v0;
      *reinterpret_cast<float2*>(dst+(size_t)(r0+8)*OUTF+col)=v1;
    }
}
} // namespace

extern "C" void kernel_launch(void* const* d_in, const int* in_sizes, int n_in,
                              void* d_out, int out_size){
  (void)in_sizes;(void)n_in;(void)out_size;
  const float* X=(const float*)d_in[0];
  const float* W=(const float*)d_in[1];
  float* out=(float*)d_out;
  kprep<<<12288,256>>>(X,W);
  cudaFuncSetAttribute(kgemm, cudaFuncAttributeMaxDynamicSharedMemorySize, SMEMSZ);
  kgemm<<<256,NTHR,SMEMSZ>>>(out);
}